// round 10
// baseline (speedup 1.0000x reference)
#include <cuda_runtime.h>
#include <cuda_fp16.h>
#include <cstdint>
#include <cstddef>

#define VOCAB 32000
#define EMB   256
#define HID   512
#define FEAT  1024
#define BATCH 32
#define TT    100
#define M_ROWS (TT*BATCH)      // 3200
#define NBLK_LSTM 128
#define N_TILES (125*25)       // 3125 vocab tiles (128m x 256n)
typedef unsigned long long ull;

// ---------------------------------------------------------------------------
// device scratch
// ---------------------------------------------------------------------------
__device__ float g_pooled[BATCH*FEAT];
__device__ float g_xg[(size_t)M_ROWS * 4 * HID];
__device__ float g_hping[2][BATCH*HID];
__device__ int   g_tok[M_ROWS];
__device__ unsigned g_barrier;
__device__ int   g_tile;

__device__ __half g_wv_f16[(size_t)VOCAB * HID];   // fp16 weights
__device__ __half g_h_f16[(size_t)M_ROWS * HID];   // fp16 h (written by LSTM role)

// ---------------------------------------------------------------------------
// helpers
// ---------------------------------------------------------------------------
__device__ __forceinline__ uint32_t smem_u32(const void* p) {
    uint32_t a;
    asm("{ .reg .u64 t; cvta.to.shared.u64 t, %1; cvt.u32.u64 %0, t; }" : "=r"(a) : "l"(p));
    return a;
}
__device__ __forceinline__ void cp_async16(uint32_t dst, const void* src) {
    asm volatile("cp.async.cg.shared.global [%0], [%1], 16;" :: "r"(dst), "l"(src) : "memory");
}
#define CP_ASYNC_COMMIT() asm volatile("cp.async.commit_group;" ::: "memory")
#define CP_ASYNC_WAIT(n)  asm volatile("cp.async.wait_group %0;" :: "n"(n) : "memory")

#define BAR_VOCAB() asm volatile("bar.sync 1, 512;" ::: "memory")
#define BAR_LSTM()  asm volatile("bar.sync 2, 128;" ::: "memory")

__device__ __forceinline__ void ldsm_x4(uint32_t& r0, uint32_t& r1, uint32_t& r2, uint32_t& r3,
                                        uint32_t addr) {
    asm volatile("ldmatrix.sync.aligned.m8n8.x4.shared.b16 {%0,%1,%2,%3}, [%4];"
                 : "=r"(r0), "=r"(r1), "=r"(r2), "=r"(r3) : "r"(addr));
}
__device__ __forceinline__ void mma_f16(float* c, uint32_t a0, uint32_t a1, uint32_t a2, uint32_t a3,
                                        uint32_t b0, uint32_t b1) {
    asm volatile("mma.sync.aligned.m16n8k16.row.col.f32.f16.f16.f32 "
                 "{%0,%1,%2,%3}, {%4,%5,%6,%7}, {%8,%9}, {%0,%1,%2,%3};"
                 : "+f"(c[0]), "+f"(c[1]), "+f"(c[2]), "+f"(c[3])
                 : "r"(a0), "r"(a1), "r"(a2), "r"(a3), "r"(b0), "r"(b1));
}

__device__ __forceinline__ ull pack2(float x, float y) {
    ull r;
    asm("mov.b64 %0, {%1, %2};" : "=l"(r) : "r"(__float_as_uint(x)), "r"(__float_as_uint(y)));
    return r;
}
__device__ __forceinline__ void ffma2(ull& d, ull a, ull b) {
    asm("fma.rn.f32x2 %0, %1, %2, %3;" : "=l"(d) : "l"(a), "l"(b), "l"(d));
}
__device__ __forceinline__ float sum2(ull p) {
    return __uint_as_float((unsigned)p) + __uint_as_float((unsigned)(p >> 32));
}

// ---------------------------------------------------------------------------
// prep / pool / h0 / weight convert
// ---------------------------------------------------------------------------
__global__ void prep_kernel(const int* __restrict__ reports) {
    int i = blockIdx.x * blockDim.x + threadIdx.x;
    if (i == 0) { g_barrier = 0u; g_tile = 0; }
    if (i < M_ROWS) {
        int t = i >> 5, b = i & 31;
        g_tok[i] = (t == 0) ? 1 : reports[b * TT + (t - 1)];
    }
}

__global__ void pool_kernel(const float* __restrict__ feat) {
    int i = blockIdx.x * blockDim.x + threadIdx.x;
    if (i < BATCH * FEAT) {
        const float* p = feat + (size_t)i * 49;
        float s = 0.f;
        #pragma unroll
        for (int j = 0; j < 49; j++) s += p[j];
        g_pooled[i] = s * (1.f / 49.f);
    }
}

__global__ void h0_kernel(const float* __restrict__ fc_w, const float* __restrict__ fc_b) {
    int i = blockIdx.x * blockDim.x + threadIdx.x;
    if (i >= BATCH * HID) return;
    int b = i >> 9, j = i & 511;
    const float* pw = fc_w + (size_t)j * FEAT;
    const float* pp = g_pooled + (size_t)b * FEAT;
    float acc = fc_b[j];
    #pragma unroll 4
    for (int k = 0; k < FEAT; k++) acc = fmaf(pw[k], pp[k], acc);
    g_hping[0][b * HID + j] = acc;
}

__global__ void cvt_wv_kernel(const float* __restrict__ src, __half* __restrict__ dst, int n4) {
    int i = blockIdx.x * blockDim.x + threadIdx.x;
    if (i >= n4) return;
    float4 v = reinterpret_cast<const float4*>(src)[i];
    reinterpret_cast<__half2*>(dst)[i*2]   = __halves2half2(__float2half_rn(v.x), __float2half_rn(v.y));
    reinterpret_cast<__half2*>(dst)[i*2+1] = __halves2half2(__float2half_rn(v.z), __float2half_rn(v.w));
}

// ---------------------------------------------------------------------------
// SIMT fp32 GEMM (gates)
// ---------------------------------------------------------------------------
__global__ __launch_bounds__(256)
void gemm_gates_kernel(const float* __restrict__ Asrc, const float* __restrict__ Bsrc,
                       const float* __restrict__ bias0, const float* __restrict__ bias1,
                       float* __restrict__ C, int N, int K, const int* __restrict__ gidx)
{
    __shared__ float As[16 * 132];
    __shared__ float Bs[16 * 132];
    const int tid = threadIdx.x;
    const int n0 = blockIdx.x * 128;
    const int m0 = blockIdx.y * 128;
    const int ty = tid >> 4;
    const int tx = tid & 15;

    ull acc[8][4];
    #pragma unroll
    for (int i = 0; i < 8; i++)
        #pragma unroll
        for (int j = 0; j < 4; j++) acc[i][j] = 0ull;

    const int ml = tid >> 2;
    const int kq = (tid & 3) * 4;
    const float* arow0 = Asrc + (size_t)gidx[m0 + ml] * K;
    const float* arow1 = Asrc + (size_t)gidx[m0 + ml + 64] * K;
    const float* brow0 = Bsrc + (size_t)(n0 + ml) * K;
    const float* brow1 = Bsrc + (size_t)(n0 + ml + 64) * K;

    for (int k0 = 0; k0 < K; k0 += 16) {
        float4 a0  = *reinterpret_cast<const float4*>(arow0 + k0 + kq);
        float4 a1  = *reinterpret_cast<const float4*>(arow1 + k0 + kq);
        float4 bb0 = *reinterpret_cast<const float4*>(brow0 + k0 + kq);
        float4 bb1 = *reinterpret_cast<const float4*>(brow1 + k0 + kq);
        __syncthreads();
        As[(kq+0)*132 + ml] = a0.x;  As[(kq+1)*132 + ml] = a0.y;
        As[(kq+2)*132 + ml] = a0.z;  As[(kq+3)*132 + ml] = a0.w;
        As[(kq+0)*132 + ml+64] = a1.x;  As[(kq+1)*132 + ml+64] = a1.y;
        As[(kq+2)*132 + ml+64] = a1.z;  As[(kq+3)*132 + ml+64] = a1.w;
        Bs[(kq+0)*132 + ml] = bb0.x; Bs[(kq+1)*132 + ml] = bb0.y;
        Bs[(kq+2)*132 + ml] = bb0.z; Bs[(kq+3)*132 + ml] = bb0.w;
        Bs[(kq+0)*132 + ml+64] = bb1.x; Bs[(kq+1)*132 + ml+64] = bb1.y;
        Bs[(kq+2)*132 + ml+64] = bb1.z; Bs[(kq+3)*132 + ml+64] = bb1.w;
        __syncthreads();

        #pragma unroll
        for (int kk = 0; kk < 16; kk++) {
            const float* ar = As + kk*132 + ty*8;
            const float* br = Bs + kk*132 + tx*8;
            float4 av0 = *reinterpret_cast<const float4*>(ar);
            float4 av1 = *reinterpret_cast<const float4*>(ar + 4);
            float4 bv0 = *reinterpret_cast<const float4*>(br);
            float4 bv1 = *reinterpret_cast<const float4*>(br + 4);
            ull bp0 = pack2(bv0.x, bv0.y);
            ull bp1 = pack2(bv0.z, bv0.w);
            ull bp2 = pack2(bv1.x, bv1.y);
            ull bp3 = pack2(bv1.z, bv1.w);
            float aa[8] = {av0.x, av0.y, av0.z, av0.w, av1.x, av1.y, av1.z, av1.w};
            #pragma unroll
            for (int i = 0; i < 8; i++) {
                ull ap = pack2(aa[i], aa[i]);
                ffma2(acc[i][0], ap, bp0);
                ffma2(acc[i][1], ap, bp1);
                ffma2(acc[i][2], ap, bp2);
                ffma2(acc[i][3], ap, bp3);
            }
        }
    }

    float bias[8];
    #pragma unroll
    for (int j = 0; j < 8; j++) {
        int n = n0 + tx*8 + j;
        bias[j] = bias0[n] + bias1[n];
    }
    #pragma unroll
    for (int i = 0; i < 8; i++) {
        int m = m0 + ty*8 + i;
        size_t base = (size_t)m * (size_t)N + (size_t)(n0 + tx*8);
        float o[8];
        #pragma unroll
        for (int j = 0; j < 4; j++) {
            o[2*j]   = __uint_as_float((unsigned)(acc[i][j]))       + bias[2*j];
            o[2*j+1] = __uint_as_float((unsigned)(acc[i][j] >> 32)) + bias[2*j+1];
        }
        *reinterpret_cast<float4*>(C + base)     = make_float4(o[0], o[1], o[2], o[3]);
        *reinterpret_cast<float4*>(C + base + 4) = make_float4(o[4], o[5], o[6], o[7]);
    }
}

// ---------------------------------------------------------------------------
// Fused persistent LSTM + vocab GEMM.
// 148 blocks x 640 threads (ONE wave, all resident -> no deadlock).
// warps 16-19 (highest wid, arbiter priority): blocks 0..127 run the LSTM.
// warps 0-15: loop over a dynamic tile queue (atomicAdd on g_tile);
//   each tile spin-waits until its 4 timesteps of h are published.
// ---------------------------------------------------------------------------
#define WS_STRIDE 516
#define LSTM_SMEM_BYTES 101248
#define VG_STAGE 49152
#define FUSED_SMEM (LSTM_SMEM_BYTES + 2*VG_STAGE)

__device__ __forceinline__ void lstm_role(float* sm, const float* __restrict__ Whh, int ltid) {
    float* ws  = sm;
    float* hs  = sm + 16*WS_STRIDE;
    float* gsm = sm + 16*WS_STRIDE + 32*WS_STRIDE;

    const int n0 = blockIdx.x * 4;

    for (int lr = 0; lr < 16; lr++) {
        int u = lr >> 2, g = lr & 3;
        const float* src = Whh + (size_t)(g * HID + n0 + u) * HID;
        for (int k = ltid; k < HID; k += 128) ws[lr * WS_STRIDE + k] = src[k];
    }

    const int rp = (ltid & 1) + ((ltid >> 5) << 1);
    const int r0 = rp * 2, r1 = r0 + 1;
    const int bp = (ltid >> 1) & 15;
    const int b0 = bp * 2, b1 = b0 + 1;
    const int cu = ltid >> 5;
    const int cb = ltid & 31;
    const int g0 = (r0 & 3) * HID + n0 + (r0 >> 2);
    const int g1 = (r1 & 3) * HID + n0 + (r1 >> 2);
    float c_reg = 0.f;

    BAR_LSTM();

    for (int t = 0; t < TT; t++) {
        const size_t xt = (size_t)t * BATCH * (4*HID);
        float x00 = __ldcg(&g_xg[xt + (size_t)b0 * (4*HID) + g0]);
        float x01 = __ldcg(&g_xg[xt + (size_t)b1 * (4*HID) + g0]);
        float x10 = __ldcg(&g_xg[xt + (size_t)b0 * (4*HID) + g1]);
        float x11 = __ldcg(&g_xg[xt + (size_t)b1 * (4*HID) + g1]);

        const float* hin = g_hping[t & 1];
        #pragma unroll 4
        for (int j = 0; j < 32; j++) {
            float4 v = __ldcg(reinterpret_cast<const float4*>(hin + j * HID + ltid * 4));
            *reinterpret_cast<float4*>(hs + j * WS_STRIDE + ltid * 4) = v;
        }
        BAR_LSTM();

        const ulonglong2* w0 = reinterpret_cast<const ulonglong2*>(ws + r0 * WS_STRIDE);
        const ulonglong2* w1 = reinterpret_cast<const ulonglong2*>(ws + r1 * WS_STRIDE);
        const ulonglong2* ha = reinterpret_cast<const ulonglong2*>(hs + b0 * WS_STRIDE);
        const ulonglong2* hb = reinterpret_cast<const ulonglong2*>(hs + b1 * WS_STRIDE);
        ull p00 = 0ull, p01 = 0ull, p10 = 0ull, p11 = 0ull;
        #pragma unroll 8
        for (int k = 0; k < HID/4; k++) {
            ulonglong2 wa = w0[k], wb = w1[k];
            ulonglong2 va = ha[k], vb = hb[k];
            ffma2(p00, wa.x, va.x); ffma2(p00, wa.y, va.y);
            ffma2(p01, wa.x, vb.x); ffma2(p01, wa.y, vb.y);
            ffma2(p10, wb.x, va.x); ffma2(p10, wb.y, va.y);
            ffma2(p11, wb.x, vb.x); ffma2(p11, wb.y, vb.y);
        }
        gsm[r0*33 + b0] = sum2(p00) + x00;
        gsm[r0*33 + b1] = sum2(p01) + x01;
        gsm[r1*33 + b0] = sum2(p10) + x10;
        gsm[r1*33 + b1] = sum2(p11) + x11;
        BAR_LSTM();

        {
            float iv = gsm[(cu*4 + 0)*33 + cb];
            float fv = gsm[(cu*4 + 1)*33 + cb];
            float gv = gsm[(cu*4 + 2)*33 + cb];
            float ov = gsm[(cu*4 + 3)*33 + cb];
            iv = 1.f / (1.f + __expf(-iv));
            fv = 1.f / (1.f + __expf(-fv));
            ov = 1.f / (1.f + __expf(-ov));
            gv = tanhf(gv);
            c_reg = fv * c_reg + iv * gv;
            float hn = ov * tanhf(c_reg);
            int nidx = n0 + cu;
            __stcg(&g_hping[(t + 1) & 1][cb * HID + nidx], hn);
            __stcg(reinterpret_cast<__half*>(&g_h_f16[((size_t)t * BATCH + cb) * HID + nidx]),
                   __float2half_rn(hn));
        }

        __threadfence();
        BAR_LSTM();
        if (ltid == 0) atomicAdd(&g_barrier, 1u);
        if (t + 1 < TT) {
            if (ltid == 0) {
                unsigned target = (unsigned)((t + 1) * NBLK_LSTM);
                while (*((volatile unsigned*)&g_barrier) < target) { __nanosleep(32); }
            }
            BAR_LSTM();
            __threadfence();
        }
    }
}

__device__ __forceinline__ void vocab_role(char* vsm_raw, const float* __restrict__ bv,
                                           float* __restrict__ out, int tid) {
    __shared__ int s_ti;
    const uint32_t smem = smem_u32(vsm_raw);
    const int wid  = tid >> 5;
    const int lane = tid & 31;
    const int wm   = wid >> 2;          // 0..3
    const int wn   = wid & 3;           // 0..3

    for (;;) {
        if (tid == 0) s_ti = atomicAdd(&g_tile, 1);
        BAR_VOCAB();
        const int ti = s_ti;
        if (ti >= N_TILES) break;
        const int yy = ti / 125;
        const int n0 = (ti - yy * 125) * 256;
        const int m0 = yy * 128;

        // wait until this tile's 4 timesteps of h are published
        if (tid == 0) {
            unsigned need = (unsigned)((yy * 4 + 4) * NBLK_LSTM);
            while (*((volatile unsigned*)&g_barrier) < need) { __nanosleep(128); }
        }
        BAR_VOCAB();
        __threadfence();

        float acc[2][8][4];
        #pragma unroll
        for (int i = 0; i < 2; i++)
            #pragma unroll
            for (int j = 0; j < 8; j++)
                #pragma unroll
                for (int q = 0; q < 4; q++) acc[i][j][q] = 0.f;

        auto load_chunk = [&](int chunk) {
            const uint32_t stage = smem + (uint32_t)(chunk & 1) * VG_STAGE;
            const int kbase = chunk * 64;
            #pragma unroll
            for (int j = 0; j < 6; j++) {
                int i = tid + j * 512;          // 0..3071
                const __half* gb;
                int grow;
                uint32_t doff;
                int cc;
                if (i < 1024) {                  // A: 128 rows x 8 chunks
                    int r  = (i >> 3) & 127;
                    cc = i & 7;
                    gb = g_h_f16;
                    grow = m0 + r;
                    doff = (uint32_t)(r * 128) + (uint32_t)(((cc ^ (r & 7)) * 16));
                } else {                         // B: 256 rows x 8 chunks
                    int jj = i - 1024;
                    int r  = (jj >> 3) & 255;
                    cc = jj & 7;
                    gb = g_wv_f16;
                    grow = n0 + r;
                    doff = 16384u + (uint32_t)(r * 128) + (uint32_t)(((cc ^ (r & 7)) * 16));
                }
                cp_async16(stage + doff, gb + (size_t)grow * HID + kbase + cc * 8);
            }
            CP_ASYNC_COMMIT();
        };

        load_chunk(0);

        for (int chunk = 0; chunk < 8; chunk++) {
            if (chunk + 1 < 8) { load_chunk(chunk + 1); CP_ASYNC_WAIT(1); }
            else               { CP_ASYNC_WAIT(0); }
            BAR_VOCAB();

            const uint32_t stage = smem + (uint32_t)(chunk & 1) * VG_STAGE;
            const uint32_t aBase = stage;
            const uint32_t bBase = stage + 16384u;

            #pragma unroll
            for (int ks = 0; ks < 4; ks++) {
                uint32_t ah[2][4];
                #pragma unroll
                for (int mt = 0; mt < 2; mt++) {
                    int row = wm * 32 + mt * 16 + (lane & 7) + ((lane >> 3) & 1) * 8;
                    int ch  = ks * 2 + (lane >> 4);
                    uint32_t off = (uint32_t)(row * 128) + (uint32_t)((ch ^ (row & 7)) * 16);
                    ldsm_x4(ah[mt][0], ah[mt][1], ah[mt][2], ah[mt][3], aBase + off);
                }
                #pragma unroll
                for (int p = 0; p < 4; p++) {
                    int g   = lane >> 3;
                    int row = wn * 64 + p * 16 + (g & 1) * 8 + (lane & 7);
                    int ch  = ks * 2 + (g >> 1);
                    uint32_t off = (uint32_t)(row * 128) + (uint32_t)((ch ^ (row & 7)) * 16);
                    uint32_t bh[2][2];
                    {
                        uint32_t r0, r1, r2, r3;
                        ldsm_x4(r0, r1, r2, r3, bBase + off);
                        bh[0][0] = r0; bh[0][1] = r2;
                        bh[1][0] = r1; bh[1][1] = r3;
                    }
                    #pragma unroll
                    for (int mt = 0; mt < 2; mt++) {
                        #pragma unroll
                        for (int q = 0; q < 2; q++) {
                            int nt = p * 2 + q;
                            mma_f16(acc[mt][nt], ah[mt][0], ah[mt][1], ah[mt][2], ah[mt][3],
                                    bh[q][0], bh[q][1]);
                        }
                    }
                }
            }
            BAR_VOCAB();
        }

        // epilogue
        #pragma unroll
        for (int mt = 0; mt < 2; mt++) {
            int gm0 = m0 + wm * 32 + mt * 16 + (lane >> 2);
            int gm1 = gm0 + 8;
            size_t ob0 = ((size_t)(gm0 & 31) * TT + (size_t)(gm0 >> 5)) * (size_t)VOCAB;
            size_t ob1 = ((size_t)(gm1 & 31) * TT + (size_t)(gm1 >> 5)) * (size_t)VOCAB;
            #pragma unroll
            for (int nt = 0; nt < 8; nt++) {
                int gn = n0 + wn * 64 + nt * 8 + (lane & 3) * 2;
                float bv0 = __ldg(bv + gn), bv1 = __ldg(bv + gn + 1);
                float2 v0 = make_float2(acc[mt][nt][0] + bv0, acc[mt][nt][1] + bv1);
                float2 v1 = make_float2(acc[mt][nt][2] + bv0, acc[mt][nt][3] + bv1);
                *reinterpret_cast<float2*>(out + ob0 + gn) = v0;
                *reinterpret_cast<float2*>(out + ob1 + gn) = v1;
            }
        }
    }
}

__global__ __launch_bounds__(640, 1)
void fused_kernel(const float* __restrict__ Whh, const float* __restrict__ bv,
                  float* __restrict__ out)
{
    extern __shared__ char sm_raw[];
    const int tid = threadIdx.x;
    if (tid >= 512) {
        if (blockIdx.x < NBLK_LSTM)
            lstm_role(reinterpret_cast<float*>(sm_raw), Whh, tid - 512);
        return;
    }
    vocab_role(sm_raw + LSTM_SMEM_BYTES, bv, out, tid);
}

// ---------------------------------------------------------------------------
// launch
// ---------------------------------------------------------------------------
extern "C" void kernel_launch(void* const* d_in, const int* in_sizes, int n_in,
                              void* d_out, int out_size) {
    const float* features  = (const float*)d_in[0];
    const int*   reports   = (const int*)  d_in[1];
    const float* emb_table = (const float*)d_in[2];
    const float* fc_w      = (const float*)d_in[3];
    const float* fc_b      = (const float*)d_in[4];
    const float* W_ih      = (const float*)d_in[5];
    const float* b_ih      = (const float*)d_in[6];
    const float* W_hh      = (const float*)d_in[7];
    const float* b_hh      = (const float*)d_in[8];
    const float* Wv        = (const float*)d_in[9];
    const float* bv        = (const float*)d_in[10];
    float* out = (float*)d_out;

    void *p_xg = nullptr, *p_tok = nullptr, *p_wv16 = nullptr;
    cudaGetSymbolAddress(&p_xg,   g_xg);
    cudaGetSymbolAddress(&p_tok,  g_tok);
    cudaGetSymbolAddress(&p_wv16, g_wv_f16);

    cudaFuncSetAttribute(fused_kernel, cudaFuncAttributeMaxDynamicSharedMemorySize, FUSED_SMEM);

    prep_kernel<<<(M_ROWS + 255) / 256, 256>>>(reports);
    pool_kernel<<<(BATCH * FEAT + 255) / 256, 256>>>(features);
    h0_kernel<<<(BATCH * HID + 255) / 256, 256>>>(fc_w, fc_b);
    {
        int n4 = VOCAB * HID / 4;
        cvt_wv_kernel<<<(n4 + 255) / 256, 256>>>(Wv, (__half*)p_wv16, n4);
    }
    gemm_gates_kernel<<<dim3(4*HID/128, M_ROWS/128), 256>>>(
        emb_table, W_ih, b_ih, b_hh, (float*)p_xg, 4*HID, EMB, (const int*)p_tok);
    // persistent fused kernel: ONE wave of 148 blocks
    fused_kernel<<<148, 640, FUSED_SMEM>>>(W_hh, bv, out);
}